// round 3
// baseline (speedup 1.0000x reference)
#include <cuda_runtime.h>
#include <cuda_bf16.h>
#include <cstdint>

#define SDIM 2304
#define CDIM 1280
#define NHEAD 20
#define DHEAD 64
#define SS ((size_t)SDIM * SDIM)
#define LDK 72                      // padded k-stride (bf16 elems) -> conflict-free frags
#define TILEB (128 * LDK * 2)       // 18432 bytes per 128-row tile

// ---------------- static scratch ----------------
__device__ __align__(256) float g_S[(size_t)NHEAD * SS];                 // 425 MB raw scores
__device__ __align__(256) __nv_bfloat16 g_Phi[(size_t)NHEAD * SS];
__device__ __align__(256) __nv_bfloat16 g_Plo[(size_t)NHEAD * SS];
__device__ __align__(256) __nv_bfloat16 g_Qhi[(size_t)NHEAD * SDIM * DHEAD];
__device__ __align__(256) __nv_bfloat16 g_Qlo[(size_t)NHEAD * SDIM * DHEAD];
__device__ __align__(256) __nv_bfloat16 g_Khi[(size_t)NHEAD * SDIM * DHEAD];
__device__ __align__(256) __nv_bfloat16 g_Klo[(size_t)NHEAD * SDIM * DHEAD];
__device__ __align__(256) __nv_bfloat16 g_Vthi[(size_t)CDIM * SDIM];     // [h*64+d][s]
__device__ __align__(256) __nv_bfloat16 g_Vtlo[(size_t)CDIM * SDIM];
__device__ __align__(256) __nv_bfloat16 g_Xhi[(size_t)SDIM * CDIM];
__device__ __align__(256) __nv_bfloat16 g_Xlo[(size_t)SDIM * CDIM];
__device__ __align__(256) __nv_bfloat16 g_Wqh[(size_t)CDIM * CDIM];      // W^T [n][k]
__device__ __align__(256) __nv_bfloat16 g_Wql[(size_t)CDIM * CDIM];
__device__ __align__(256) __nv_bfloat16 g_Wkh[(size_t)CDIM * CDIM];
__device__ __align__(256) __nv_bfloat16 g_Wkl[(size_t)CDIM * CDIM];
__device__ __align__(256) __nv_bfloat16 g_Wvh[(size_t)CDIM * CDIM];
__device__ __align__(256) __nv_bfloat16 g_Wvl[(size_t)CDIM * CDIM];
__device__ __align__(256) __nv_bfloat16 g_Woh[(size_t)CDIM * CDIM];
__device__ __align__(256) __nv_bfloat16 g_Wol[(size_t)CDIM * CDIM];
__device__ __align__(256) __nv_bfloat16 g_Ch[(size_t)SDIM * CDIM];
__device__ __align__(256) __nv_bfloat16 g_Cl[(size_t)SDIM * CDIM];
__device__ __align__(256) unsigned char g_mask[SS];
__device__ int g_mask_mode;

// ---------------- helpers ----------------
__device__ __forceinline__ uint32_t smem_u32(const void* p) {
    uint32_t a;
    asm("{ .reg .u64 t; cvta.to.shared.u64 t, %1; cvt.u32.u64 %0, t; }" : "=r"(a) : "l"(p));
    return a;
}
__device__ __forceinline__ uint32_t lds32(uint32_t a) {
    uint32_t v;
    asm volatile("ld.shared.b32 %0,[%1];" : "=r"(v) : "r"(a));
    return v;
}
__device__ __forceinline__ void mma16816(float c[4], uint32_t a0, uint32_t a1, uint32_t a2, uint32_t a3,
                                         uint32_t b0, uint32_t b1) {
    asm volatile(
        "mma.sync.aligned.m16n8k16.row.col.f32.bf16.bf16.f32 "
        "{%0,%1,%2,%3},{%4,%5,%6,%7},{%8,%9},{%0,%1,%2,%3};"
        : "+f"(c[0]), "+f"(c[1]), "+f"(c[2]), "+f"(c[3])
        : "r"(a0), "r"(a1), "r"(a2), "r"(a3), "r"(b0), "r"(b1));
}
// copy rows x 64 bf16 tile from global (strideElems) to smem row-major with LDK padding
__device__ __forceinline__ void copy_tile(uint32_t dstBase, const __nv_bfloat16* __restrict__ g,
                                          int strideElems, int rows, int tid) {
    int total = rows * 8;
    for (int i = tid; i < total; i += 256) {
        int r = i >> 3, c = (i & 7) * 16;
        uint4 v = *(const uint4*)((const char*)g + (size_t)r * strideElems * 2 + c);
        uint32_t d = dstBase + (uint32_t)(r * (LDK * 2) + c);
        asm volatile("st.shared.v4.b32 [%0],{%1,%2,%3,%4};" :: "r"(d), "r"(v.x), "r"(v.y), "r"(v.z), "r"(v.w));
    }
}
__device__ __forceinline__ void split2(float a, float b, __nv_bfloat162& hi, __nv_bfloat162& lo) {
    __nv_bfloat16 ha = __float2bfloat16(a), hb = __float2bfloat16(b);
    hi = __halves2bfloat162(ha, hb);
    lo = __halves2bfloat162(__float2bfloat16(a - __bfloat162float(ha)),
                            __float2bfloat16(b - __bfloat162float(hb)));
}

// ---------------- mask detect/normalize ----------------
__global__ void detect_mask_kernel(const unsigned int* __restrict__ m) {
    if (threadIdx.x != 0) return;
    bool all01 = true, allf = true;
    #pragma unroll 1
    for (int i = 0; i < 256; i++) {
        unsigned int w = m[i * 997 + 1];
        if (!(w == 0u || w == 1u)) all01 = false;
        if (!(w == 0u || w == 0x3F800000u)) allf = false;
    }
    g_mask_mode = (all01 || allf) ? 1 : 2;
}
__global__ void norm_mask_kernel(const void* __restrict__ m) {
    size_t i = (size_t)blockIdx.x * 256 + threadIdx.x;
    if (i >= SS) return;
    if (g_mask_mode == 1) g_mask[i] = (((const unsigned int*)m)[i] != 0u) ? 1 : 0;
    else                  g_mask[i] = (((const unsigned char*)m)[i] != 0) ? 1 : 0;
}

// ---------------- preprocessing ----------------
__global__ void conv_x_kernel(const float* __restrict__ X) {
    size_t i = (size_t)blockIdx.x * 256 + threadIdx.x;
    if (i >= (size_t)SDIM * CDIM / 2) return;
    float2 v = *(const float2*)(X + 2 * i);
    __nv_bfloat162 h, l;
    split2(v.x, v.y, h, l);
    *(__nv_bfloat162*)(g_Xhi + 2 * i) = h;
    *(__nv_bfloat162*)(g_Xlo + 2 * i) = l;
}
__global__ void transpose_w_kernel(const float* __restrict__ W,
                                   __nv_bfloat16* __restrict__ Th, __nv_bfloat16* __restrict__ Tl) {
    __shared__ float t[32][33];
    int bx = blockIdx.x * 32, by = blockIdx.y * 32;
    int tx = threadIdx.x, ty = threadIdx.y;
    #pragma unroll
    for (int i = 0; i < 32; i += 8)
        t[ty + i][tx] = W[(size_t)(by + ty + i) * CDIM + bx + tx];
    __syncthreads();
    #pragma unroll
    for (int i = 0; i < 32; i += 8) {
        float v = t[tx][ty + i];
        size_t o = (size_t)(bx + ty + i) * CDIM + by + tx;   // WT[n][k] = W[k][n]
        __nv_bfloat16 hv = __float2bfloat16(v);
        Th[o] = hv;
        Tl[o] = __float2bfloat16(v - __bfloat162float(hv));
    }
}

// ============ generic 128x128 MMA GEMM (A[m][k] x B^T[n][k]) ============
// mode 0: bf16 hi/lo head-major [h][s][d]; mode 1: bf16 hi/lo transposed (o = n*SDIM+m);
// mode 2: fp32 + bias to Ofp
__global__ void __launch_bounds__(256) mma_gemm128(
    const __nv_bfloat16* __restrict__ Ah, const __nv_bfloat16* __restrict__ Al, int lda,
    const __nv_bfloat16* __restrict__ Bh, const __nv_bfloat16* __restrict__ Bl, int ldb,
    int kChunks, int mode,
    __nv_bfloat16* __restrict__ Oh, __nv_bfloat16* __restrict__ Ol,
    const float* __restrict__ bias, float* __restrict__ Ofp)
{
    extern __shared__ char smem[];
    uint32_t sb = smem_u32(smem);
    const uint32_t sAh = sb, sAl = sAh + TILEB, sBh = sAl + TILEB, sBl = sBh + TILEB;
    const int tid = threadIdx.x, wid = tid >> 5, lane = tid & 31;
    const int wr = wid >> 2, wc = wid & 3;
    const int g = lane >> 2, tig = lane & 3;
    const int mBase = blockIdx.y * 128, nBase = blockIdx.x * 128;

    float acc[4][4][4];
    #pragma unroll
    for (int i = 0; i < 4; i++)
        #pragma unroll
        for (int j = 0; j < 4; j++)
            #pragma unroll
            for (int k = 0; k < 4; k++) acc[i][j][k] = 0.f;

    uint32_t aRow[4], bRow[4];
    #pragma unroll
    for (int fi = 0; fi < 4; fi++) aRow[fi] = (uint32_t)((wr * 64 + fi * 16 + g) * (LDK * 2)) + tig * 4;
    #pragma unroll
    for (int fj = 0; fj < 4; fj++) bRow[fj] = (uint32_t)((wc * 32 + fj * 8 + g) * (LDK * 2)) + tig * 4;

    const __nv_bfloat16* pAh = Ah + (size_t)mBase * lda;
    const __nv_bfloat16* pAl = Al + (size_t)mBase * lda;
    const __nv_bfloat16* pBh = Bh + (size_t)nBase * ldb;
    const __nv_bfloat16* pBl = Bl + (size_t)nBase * ldb;

    for (int ch = 0; ch < kChunks; ch++) {
        int kc = ch * 64;
        copy_tile(sAh, pAh + kc, lda, 128, tid);
        copy_tile(sAl, pAl + kc, lda, 128, tid);
        copy_tile(sBh, pBh + kc, ldb, 128, tid);
        copy_tile(sBl, pBl + kc, ldb, 128, tid);
        __syncthreads();
        #pragma unroll
        for (int ks = 0; ks < 4; ks++) {
            uint32_t koff = ks * 32;
            uint32_t ah[4][4], bh[4][2], bl[4][2];
            #pragma unroll
            for (int fi = 0; fi < 4; fi++) {
                uint32_t a = sAh + aRow[fi] + koff;
                ah[fi][0] = lds32(a);         ah[fi][1] = lds32(a + 8 * LDK * 2);
                ah[fi][2] = lds32(a + 16);    ah[fi][3] = lds32(a + 8 * LDK * 2 + 16);
            }
            #pragma unroll
            for (int fj = 0; fj < 4; fj++) {
                uint32_t b = sBh + bRow[fj] + koff;
                bh[fj][0] = lds32(b);  bh[fj][1] = lds32(b + 16);
                uint32_t b2 = sBl + bRow[fj] + koff;
                bl[fj][0] = lds32(b2); bl[fj][1] = lds32(b2 + 16);
            }
            #pragma unroll
            for (int fi = 0; fi < 4; fi++)
                #pragma unroll
                for (int fj = 0; fj < 4; fj++) {
                    mma16816(acc[fi][fj], ah[fi][0], ah[fi][1], ah[fi][2], ah[fi][3], bh[fj][0], bh[fj][1]);
                    mma16816(acc[fi][fj], ah[fi][0], ah[fi][1], ah[fi][2], ah[fi][3], bl[fj][0], bl[fj][1]);
                }
            #pragma unroll
            for (int fi = 0; fi < 4; fi++) {
                uint32_t a = sAl + aRow[fi] + koff;
                ah[fi][0] = lds32(a);         ah[fi][1] = lds32(a + 8 * LDK * 2);
                ah[fi][2] = lds32(a + 16);    ah[fi][3] = lds32(a + 8 * LDK * 2 + 16);
            }
            #pragma unroll
            for (int fi = 0; fi < 4; fi++)
                #pragma unroll
                for (int fj = 0; fj < 4; fj++)
                    mma16816(acc[fi][fj], ah[fi][0], ah[fi][1], ah[fi][2], ah[fi][3], bh[fj][0], bh[fj][1]);
        }
        __syncthreads();
    }

    #pragma unroll
    for (int fi = 0; fi < 4; fi++) {
        #pragma unroll
        for (int fj = 0; fj < 4; fj++) {
            int m0 = mBase + wr * 64 + fi * 16 + g;
            int n0 = nBase + wc * 32 + fj * 8 + tig * 2;
            float c0 = acc[fi][fj][0], c1 = acc[fi][fj][1];
            float c2 = acc[fi][fj][2], c3 = acc[fi][fj][3];
            if (mode == 0) {
                int h = n0 >> 6, dd = n0 & 63;
                size_t o0 = ((size_t)h * SDIM + m0) * DHEAD + dd;
                size_t o1 = ((size_t)h * SDIM + m0 + 8) * DHEAD + dd;
                __nv_bfloat162 hv, lv;
                split2(c0, c1, hv, lv);
                *(__nv_bfloat162*)(Oh + o0) = hv; *(__nv_bfloat162*)(Ol + o0) = lv;
                split2(c2, c3, hv, lv);
                *(__nv_bfloat162*)(Oh + o1) = hv; *(__nv_bfloat162*)(Ol + o1) = lv;
            } else if (mode == 1) {
                size_t o00 = (size_t)n0 * SDIM + m0;
                size_t o01 = (size_t)(n0 + 1) * SDIM + m0;
                __nv_bfloat16 h0 = __float2bfloat16(c0);
                __nv_bfloat16 h1 = __float2bfloat16(c1);
                __nv_bfloat16 h2 = __float2bfloat16(c2);
                __nv_bfloat16 h3 = __float2bfloat16(c3);
                Oh[o00] = h0;     Ol[o00] = __float2bfloat16(c0 - __bfloat162float(h0));
                Oh[o01] = h1;     Ol[o01] = __float2bfloat16(c1 - __bfloat162float(h1));
                Oh[o00 + 8] = h2; Ol[o00 + 8] = __float2bfloat16(c2 - __bfloat162float(h2));
                Oh[o01 + 8] = h3; Ol[o01 + 8] = __float2bfloat16(c3 - __bfloat162float(h3));
            } else {
                float2 bv = *(const float2*)(bias + n0);
                float2 r0 = make_float2(c0 + bv.x, c1 + bv.y);
                float2 r1 = make_float2(c2 + bv.x, c3 + bv.y);
                *(float2*)(Ofp + (size_t)m0 * CDIM + n0) = r0;
                *(float2*)(Ofp + (size_t)(m0 + 8) * CDIM + n0) = r1;
            }
        }
    }
}

// ============ scores: S[h] = 0.125 * Q K^T + mask (K=64) ============
__global__ void __launch_bounds__(256) mma_scores() {
    extern __shared__ char smem[];
    uint32_t sb = smem_u32(smem);
    const uint32_t sAh = sb, sAl = sAh + TILEB, sBh = sAl + TILEB, sBl = sBh + TILEB;
    const int tid = threadIdx.x, wid = tid >> 5, lane = tid & 31;
    const int wr = wid >> 2, wc = wid & 3;
    const int g = lane >> 2, tig = lane & 3;
    const int h = blockIdx.z;
    const int mBase = blockIdx.y * 128, nBase = blockIdx.x * 128;

    float acc[4][4][4];
    #pragma unroll
    for (int i = 0; i < 4; i++)
        #pragma unroll
        for (int j = 0; j < 4; j++)
            #pragma unroll
            for (int k = 0; k < 4; k++) acc[i][j][k] = 0.f;

    uint32_t aRow[4], bRow[4];
    #pragma unroll
    for (int fi = 0; fi < 4; fi++) aRow[fi] = (uint32_t)((wr * 64 + fi * 16 + g) * (LDK * 2)) + tig * 4;
    #pragma unroll
    for (int fj = 0; fj < 4; fj++) bRow[fj] = (uint32_t)((wc * 32 + fj * 8 + g) * (LDK * 2)) + tig * 4;

    copy_tile(sAh, g_Qhi + ((size_t)h * SDIM + mBase) * DHEAD, DHEAD, 128, tid);
    copy_tile(sAl, g_Qlo + ((size_t)h * SDIM + mBase) * DHEAD, DHEAD, 128, tid);
    copy_tile(sBh, g_Khi + ((size_t)h * SDIM + nBase) * DHEAD, DHEAD, 128, tid);
    copy_tile(sBl, g_Klo + ((size_t)h * SDIM + nBase) * DHEAD, DHEAD, 128, tid);
    __syncthreads();
    #pragma unroll
    for (int ks = 0; ks < 4; ks++) {
        uint32_t koff = ks * 32;
        uint32_t ah[4][4], bh[4][2], bl[4][2];
        #pragma unroll
        for (int fi = 0; fi < 4; fi++) {
            uint32_t a = sAh + aRow[fi] + koff;
            ah[fi][0] = lds32(a);      ah[fi][1] = lds32(a + 8 * LDK * 2);
            ah[fi][2] = lds32(a + 16); ah[fi][3] = lds32(a + 8 * LDK * 2 + 16);
        }
        #pragma unroll
        for (int fj = 0; fj < 4; fj++) {
            uint32_t b = sBh + bRow[fj] + koff;
            bh[fj][0] = lds32(b);  bh[fj][1] = lds32(b + 16);
            uint32_t b2 = sBl + bRow[fj] + koff;
            bl[fj][0] = lds32(b2); bl[fj][1] = lds32(b2 + 16);
        }
        #pragma unroll
        for (int fi = 0; fi < 4; fi++)
            #pragma unroll
            for (int fj = 0; fj < 4; fj++) {
                mma16816(acc[fi][fj], ah[fi][0], ah[fi][1], ah[fi][2], ah[fi][3], bh[fj][0], bh[fj][1]);
                mma16816(acc[fi][fj], ah[fi][0], ah[fi][1], ah[fi][2], ah[fi][3], bl[fj][0], bl[fj][1]);
            }
        #pragma unroll
        for (int fi = 0; fi < 4; fi++) {
            uint32_t a = sAl + aRow[fi] + koff;
            ah[fi][0] = lds32(a);      ah[fi][1] = lds32(a + 8 * LDK * 2);
            ah[fi][2] = lds32(a + 16); ah[fi][3] = lds32(a + 8 * LDK * 2 + 16);
        }
        #pragma unroll
        for (int fi = 0; fi < 4; fi++)
            #pragma unroll
            for (int fj = 0; fj < 4; fj++)
                mma16816(acc[fi][fj], ah[fi][0], ah[fi][1], ah[fi][2], ah[fi][3], bh[fj][0], bh[fj][1]);
    }

    float* Sout = g_S + (size_t)h * SS;
    #pragma unroll
    for (int fi = 0; fi < 4; fi++)
        #pragma unroll
        for (int fj = 0; fj < 4; fj++) {
            int m0 = mBase + wr * 64 + fi * 16 + g;
            int n0 = nBase + wc * 32 + fj * 8 + tig * 2;
            const unsigned char* mk0 = g_mask + (size_t)m0 * SDIM + n0;
            const unsigned char* mk1 = g_mask + (size_t)(m0 + 8) * SDIM + n0;
            float2 r0, r1;
            r0.x = mk0[0] ? acc[fi][fj][0] * 0.125f : -1e30f;
            r0.y = mk0[1] ? acc[fi][fj][1] * 0.125f : -1e30f;
            r1.x = mk1[0] ? acc[fi][fj][2] * 0.125f : -1e30f;
            r1.y = mk1[1] ? acc[fi][fj][3] * 0.125f : -1e30f;
            *(float2*)(Sout + (size_t)m0 * SDIM + n0) = r0;
            *(float2*)(Sout + (size_t)(m0 + 8) * SDIM + n0) = r1;
        }
}

// ============ softmax: g_S -> g_Phi/g_Plo ============
__global__ void __launch_bounds__(256) softmax_kernel() {
    const int q = blockIdx.x, h = blockIdx.y;
    const float* row = g_S + ((size_t)h * SDIM + q) * SDIM;
    const int tid = threadIdx.x;

    float v[9];
    float mx = -1e30f;
    #pragma unroll
    for (int i = 0; i < 9; i++) { v[i] = row[tid + i * 256]; mx = fmaxf(mx, v[i]); }
    __shared__ float red[256];
    red[tid] = mx; __syncthreads();
    #pragma unroll
    for (int s = 128; s > 0; s >>= 1) { if (tid < s) red[tid] = fmaxf(red[tid], red[tid + s]); __syncthreads(); }
    mx = red[0]; __syncthreads();

    float sum = 0.f;
    #pragma unroll
    for (int i = 0; i < 9; i++) { v[i] = __expf(v[i] - mx); sum += v[i]; }
    red[tid] = sum; __syncthreads();
    #pragma unroll
    for (int s = 128; s > 0; s >>= 1) { if (tid < s) red[tid] += red[tid + s]; __syncthreads(); }
    float inv = 1.f / red[0];

    size_t obase = (size_t)h * SS + (size_t)q * SDIM;
    #pragma unroll
    for (int i = 0; i < 9; i++) {
        float p = v[i] * inv;
        __nv_bfloat16 hp = __float2bfloat16(p);
        size_t o = obase + tid + i * 256;
        g_Phi[o] = hp;
        g_Plo[o] = __float2bfloat16(p - __bfloat162float(hp));
    }
}

// ============ PV: Ctx[:, h*64:] = P_h @ V_h  (N=64, K=2304) ============
__global__ void __launch_bounds__(256) mma_pv() {
    extern __shared__ char smem[];
    uint32_t sb = smem_u32(smem);
    const uint32_t sAh = sb, sAl = sAh + TILEB;
    const uint32_t sBh = sAl + TILEB, sBl = sBh + 64 * LDK * 2;
    const int tid = threadIdx.x, wid = tid >> 5, lane = tid & 31;
    const int wr = wid >> 1, wc = wid & 1;
    const int g = lane >> 2, tig = lane & 3;
    const int h = blockIdx.y;
    const int mBase = blockIdx.x * 128;

    float acc[2][4][4];
    #pragma unroll
    for (int i = 0; i < 2; i++)
        #pragma unroll
        for (int j = 0; j < 4; j++)
            #pragma unroll
            for (int k = 0; k < 4; k++) acc[i][j][k] = 0.f;

    uint32_t aRow[2], bRow[4];
    #pragma unroll
    for (int fi = 0; fi < 2; fi++) aRow[fi] = (uint32_t)((wr * 32 + fi * 16 + g) * (LDK * 2)) + tig * 4;
    #pragma unroll
    for (int fj = 0; fj < 4; fj++) bRow[fj] = (uint32_t)((wc * 32 + fj * 8 + g) * (LDK * 2)) + tig * 4;

    const __nv_bfloat16* pAh = g_Phi + (size_t)h * SS + (size_t)mBase * SDIM;
    const __nv_bfloat16* pAl = g_Plo + (size_t)h * SS + (size_t)mBase * SDIM;
    const __nv_bfloat16* pBh = g_Vthi + (size_t)h * DHEAD * SDIM;
    const __nv_bfloat16* pBl = g_Vtlo + (size_t)h * DHEAD * SDIM;

    for (int ch = 0; ch < SDIM / 64; ch++) {
        int kc = ch * 64;
        copy_tile(sAh, pAh + kc, SDIM, 128, tid);
        copy_tile(sAl, pAl + kc, SDIM, 128, tid);
        copy_tile(sBh, pBh + kc, SDIM, 64, tid);
        copy_tile(sBl, pBl + kc, SDIM, 64, tid);
        __syncthreads();
        #pragma unroll
        for (int ks = 0; ks < 4; ks++) {
            uint32_t koff = ks * 32;
            uint32_t ah[2][4], bh[4][2], bl[4][2];
            #pragma unroll
            for (int fi = 0; fi < 2; fi++) {
                uint32_t a = sAh + aRow[fi] + koff;
                ah[fi][0] = lds32(a);      ah[fi][1] = lds32(a + 8 * LDK * 2);
                ah[fi][2] = lds32(a + 16); ah[fi][3] = lds32(a + 8 * LDK * 2 + 16);
            }
            #pragma unroll
            for (int fj = 0; fj < 4; fj++) {
                uint32_t b = sBh + bRow[fj] + koff;
                bh[fj][0] = lds32(b);  bh[fj][1] = lds32(b + 16);
                uint32_t b2 = sBl + bRow[fj] + koff;
                bl[fj][0] = lds32(b2); bl[fj][1] = lds32(b2 + 16);
            }
            #pragma unroll
            for (int fi = 0; fi < 2; fi++)
                #pragma unroll
                for (int fj = 0; fj < 4; fj++) {
                    mma16816(acc[fi][fj], ah[fi][0], ah[fi][1], ah[fi][2], ah[fi][3], bh[fj][0], bh[fj][1]);
                    mma16816(acc[fi][fj], ah[fi][0], ah[fi][1], ah[fi][2], ah[fi][3], bl[fj][0], bl[fj][1]);
                }
            #pragma unroll
            for (int fi = 0; fi < 2; fi++) {
                uint32_t a = sAl + aRow[fi] + koff;
                ah[fi][0] = lds32(a);      ah[fi][1] = lds32(a + 8 * LDK * 2);
                ah[fi][2] = lds32(a + 16); ah[fi][3] = lds32(a + 8 * LDK * 2 + 16);
            }
            #pragma unroll
            for (int fi = 0; fi < 2; fi++)
                #pragma unroll
                for (int fj = 0; fj < 4; fj++)
                    mma16816(acc[fi][fj], ah[fi][0], ah[fi][1], ah[fi][2], ah[fi][3], bh[fj][0], bh[fj][1]);
        }
        __syncthreads();
    }

    #pragma unroll
    for (int fi = 0; fi < 2; fi++)
        #pragma unroll
        for (int fj = 0; fj < 4; fj++) {
            int m0 = mBase + wr * 32 + fi * 16 + g;
            int c = h * DHEAD + wc * 32 + fj * 8 + tig * 2;
            __nv_bfloat162 hv, lv;
            split2(acc[fi][fj][0], acc[fi][fj][1], hv, lv);
            *(__nv_bfloat162*)(g_Ch + (size_t)m0 * CDIM + c) = hv;
            *(__nv_bfloat162*)(g_Cl + (size_t)m0 * CDIM + c) = lv;
            split2(acc[fi][fj][2], acc[fi][fj][3], hv, lv);
            *(__nv_bfloat162*)(g_Ch + (size_t)(m0 + 8) * CDIM + c) = hv;
            *(__nv_bfloat162*)(g_Cl + (size_t)(m0 + 8) * CDIM + c) = lv;
        }
}

// ---------------- launcher ----------------
extern "C" void kernel_launch(void* const* d_in, const int* in_sizes, int n_in,
                              void* d_out, int out_size) {
    const float* hidden = (const float*)d_in[0];
    const void*  mask   = d_in[1];
    const float* Wq     = (const float*)d_in[2];
    const float* Wk     = (const float*)d_in[3];
    const float* Wv     = (const float*)d_in[4];
    const float* Wo     = (const float*)d_in[5];
    const float* bo     = (const float*)d_in[6];
    float* out = (float*)d_out;

    __nv_bfloat16 *xh, *xl, *wqh, *wql, *wkh, *wkl, *wvh, *wvl, *woh, *wol;
    __nv_bfloat16 *qh, *ql, *kh, *kl, *vth, *vtl, *chh, *cll;
    cudaGetSymbolAddress((void**)&xh,  g_Xhi);  cudaGetSymbolAddress((void**)&xl,  g_Xlo);
    cudaGetSymbolAddress((void**)&wqh, g_Wqh);  cudaGetSymbolAddress((void**)&wql, g_Wql);
    cudaGetSymbolAddress((void**)&wkh, g_Wkh);  cudaGetSymbolAddress((void**)&wkl, g_Wkl);
    cudaGetSymbolAddress((void**)&wvh, g_Wvh);  cudaGetSymbolAddress((void**)&wvl, g_Wvl);
    cudaGetSymbolAddress((void**)&woh, g_Woh);  cudaGetSymbolAddress((void**)&wol, g_Wol);
    cudaGetSymbolAddress((void**)&qh,  g_Qhi);  cudaGetSymbolAddress((void**)&ql,  g_Qlo);
    cudaGetSymbolAddress((void**)&kh,  g_Khi);  cudaGetSymbolAddress((void**)&kl,  g_Klo);
    cudaGetSymbolAddress((void**)&vth, g_Vthi); cudaGetSymbolAddress((void**)&vtl, g_Vtlo);
    cudaGetSymbolAddress((void**)&chh, g_Ch);   cudaGetSymbolAddress((void**)&cll, g_Cl);

    const int smemBig = 4 * TILEB;                       // 73728
    const int smemPv  = 2 * TILEB + 2 * 64 * LDK * 2;    // 55296
    cudaFuncSetAttribute(mma_gemm128, cudaFuncAttributeMaxDynamicSharedMemorySize, smemBig);
    cudaFuncSetAttribute(mma_scores,  cudaFuncAttributeMaxDynamicSharedMemorySize, smemBig);
    cudaFuncSetAttribute(mma_pv,      cudaFuncAttributeMaxDynamicSharedMemorySize, smemPv);

    // preprocessing
    detect_mask_kernel<<<1, 32>>>((const unsigned int*)mask);
    norm_mask_kernel<<<(int)((SS + 255) / 256), 256>>>(mask);
    conv_x_kernel<<<(int)(((size_t)SDIM * CDIM / 2 + 255) / 256), 256>>>(hidden);
    dim3 tb(32, 8), tg(CDIM / 32, CDIM / 32);
    transpose_w_kernel<<<tg, tb>>>(Wq, wqh, wql);
    transpose_w_kernel<<<tg, tb>>>(Wk, wkh, wkl);
    transpose_w_kernel<<<tg, tb>>>(Wv, wvh, wvl);
    transpose_w_kernel<<<tg, tb>>>(Wo, woh, wol);

    // projections
    dim3 gProj(CDIM / 128, SDIM / 128);
    mma_gemm128<<<gProj, 256, smemBig>>>(xh, xl, CDIM, wqh, wql, CDIM, CDIM / 64, 0, qh, ql, nullptr, nullptr);
    mma_gemm128<<<gProj, 256, smemBig>>>(xh, xl, CDIM, wkh, wkl, CDIM, CDIM / 64, 0, kh, kl, nullptr, nullptr);
    mma_gemm128<<<gProj, 256, smemBig>>>(xh, xl, CDIM, wvh, wvl, CDIM, CDIM / 64, 1, vth, vtl, nullptr, nullptr);

    // attention
    dim3 gSc(SDIM / 128, SDIM / 128, NHEAD);
    mma_scores<<<gSc, 256, smemBig>>>();
    dim3 gSm(SDIM, NHEAD);
    softmax_kernel<<<gSm, 256>>>();
    dim3 gPv(SDIM / 128, NHEAD);
    mma_pv<<<gPv, 256, smemPv>>>();

    // output projection
    dim3 gOut(CDIM / 128, SDIM / 128);
    mma_gemm128<<<gOut, 256, smemBig>>>(chh, cll, CDIM, woh, wol, CDIM, CDIM / 64, 2, nullptr, nullptr, bo, out);
}

// round 4
// speedup vs baseline: 2.6592x; 2.6592x over previous
#include <cuda_runtime.h>
#include <cuda_bf16.h>
#include <cstdint>

#define SDIM 2304
#define CDIM 1280
#define NHEAD 20
#define DHEAD 64
#define SS ((size_t)SDIM * SDIM)
#define LDK 72                       // padded row stride (elems) for 64-wide tiles: 144B
#define STRB 144
#define LDVB 272                     // V^T tile row stride bytes (128 keys*2B + 16 pad)
#define TILEB (128 * STRB)           // 18432

// ---------------- static scratch ----------------
__device__ __align__(256) __nv_bfloat16 g_Qhi[(size_t)NHEAD * SDIM * DHEAD];
__device__ __align__(256) __nv_bfloat16 g_Qlo[(size_t)NHEAD * SDIM * DHEAD];
__device__ __align__(256) __nv_bfloat16 g_Khi[(size_t)NHEAD * SDIM * DHEAD];
__device__ __align__(256) __nv_bfloat16 g_Klo[(size_t)NHEAD * SDIM * DHEAD];
__device__ __align__(256) __nv_bfloat16 g_Vthi[(size_t)CDIM * SDIM];   // [h*64+d][s]
__device__ __align__(256) __nv_bfloat16 g_Vtlo[(size_t)CDIM * SDIM];
__device__ __align__(256) __nv_bfloat16 g_Xhi[(size_t)SDIM * CDIM];
__device__ __align__(256) __nv_bfloat16 g_Xlo[(size_t)SDIM * CDIM];
__device__ __align__(256) __nv_bfloat16 g_Wqh[(size_t)CDIM * CDIM];    // W^T [n][k]
__device__ __align__(256) __nv_bfloat16 g_Wql[(size_t)CDIM * CDIM];
__device__ __align__(256) __nv_bfloat16 g_Wkh[(size_t)CDIM * CDIM];
__device__ __align__(256) __nv_bfloat16 g_Wkl[(size_t)CDIM * CDIM];
__device__ __align__(256) __nv_bfloat16 g_Wvh[(size_t)CDIM * CDIM];
__device__ __align__(256) __nv_bfloat16 g_Wvl[(size_t)CDIM * CDIM];
__device__ __align__(256) __nv_bfloat16 g_Woh[(size_t)CDIM * CDIM];
__device__ __align__(256) __nv_bfloat16 g_Wol[(size_t)CDIM * CDIM];
__device__ __align__(256) __nv_bfloat16 g_Ch[(size_t)SDIM * CDIM];
__device__ __align__(256) __nv_bfloat16 g_Cl[(size_t)SDIM * CDIM];
__device__ __align__(256) unsigned char g_mask[SS];
__device__ int g_mask_mode;

// ---------------- helpers ----------------
__device__ __forceinline__ uint32_t smem_u32(const void* p) {
    uint32_t a;
    asm("{ .reg .u64 t; cvta.to.shared.u64 t, %1; cvt.u32.u64 %0, t; }" : "=r"(a) : "l"(p));
    return a;
}
#define CPA16(dst, src) asm volatile("cp.async.cg.shared.global [%0], [%1], 16;" :: "r"(dst), "l"(src))
#define CP_COMMIT()     asm volatile("cp.async.commit_group;" ::: "memory")
#define CP_WAIT(n)      asm volatile("cp.async.wait_group %0;" :: "n"(n) : "memory")

__device__ __forceinline__ void ldsm4(uint32_t addr, uint32_t r[4]) {
    asm volatile("ldmatrix.sync.aligned.m8n8.x4.shared.b16 {%0,%1,%2,%3},[%4];"
        : "=r"(r[0]), "=r"(r[1]), "=r"(r[2]), "=r"(r[3]) : "r"(addr));
}
// base + row-block rbase, 16 rows via lane&15, k-halves via lane>>4
__device__ __forceinline__ uint32_t ldaddr(uint32_t base, int rbase, int strideB, int kByte, int lane) {
    return base + (uint32_t)((rbase + (lane & 15)) * strideB + kByte + ((lane >> 4) << 4));
}
__device__ __forceinline__ void MMA(float c[4], const uint32_t a[4], uint32_t b0, uint32_t b1) {
    asm volatile(
        "mma.sync.aligned.m16n8k16.row.col.f32.bf16.bf16.f32 "
        "{%0,%1,%2,%3},{%4,%5,%6,%7},{%8,%9},{%0,%1,%2,%3};"
        : "+f"(c[0]), "+f"(c[1]), "+f"(c[2]), "+f"(c[3])
        : "r"(a[0]), "r"(a[1]), "r"(a[2]), "r"(a[3]), "r"(b0), "r"(b1));
}
__device__ __forceinline__ uint32_t packbf2(float x, float y) {
    __nv_bfloat162 t = __floats2bfloat162_rn(x, y);
    return *(uint32_t*)&t;
}
__device__ __forceinline__ void split2(float a, float b, __nv_bfloat162& hi, __nv_bfloat162& lo) {
    __nv_bfloat16 ha = __float2bfloat16(a), hb = __float2bfloat16(b);
    hi = __halves2bfloat162(ha, hb);
    lo = __halves2bfloat162(__float2bfloat16(a - __bfloat162float(ha)),
                            __float2bfloat16(b - __bfloat162float(hb)));
}

// ---------------- mask detect/normalize ----------------
__global__ void detect_mask_kernel(const unsigned int* __restrict__ m) {
    if (threadIdx.x != 0) return;
    bool all01 = true, allf = true;
    #pragma unroll 1
    for (int i = 0; i < 256; i++) {
        unsigned int w = m[i * 997 + 1];
        if (!(w == 0u || w == 1u)) all01 = false;
        if (!(w == 0u || w == 0x3F800000u)) allf = false;
    }
    g_mask_mode = (all01 || allf) ? 1 : 2;
}
__global__ void norm_mask_kernel(const void* __restrict__ m) {
    size_t i = (size_t)blockIdx.x * 256 + threadIdx.x;
    if (i >= SS) return;
    if (g_mask_mode == 1) g_mask[i] = (((const unsigned int*)m)[i] != 0u) ? 1 : 0;
    else                  g_mask[i] = (((const unsigned char*)m)[i] != 0) ? 1 : 0;
}

// ---------------- preprocessing ----------------
__global__ void conv_x_kernel(const float* __restrict__ X) {
    size_t i = (size_t)blockIdx.x * 256 + threadIdx.x;
    if (i >= (size_t)SDIM * CDIM / 2) return;
    float2 v = *(const float2*)(X + 2 * i);
    __nv_bfloat162 h, l;
    split2(v.x, v.y, h, l);
    *(__nv_bfloat162*)(g_Xhi + 2 * i) = h;
    *(__nv_bfloat162*)(g_Xlo + 2 * i) = l;
}
__global__ void transpose_w_kernel(const float* __restrict__ W,
                                   __nv_bfloat16* __restrict__ Th, __nv_bfloat16* __restrict__ Tl) {
    __shared__ float t[32][33];
    int bx = blockIdx.x * 32, by = blockIdx.y * 32;
    int tx = threadIdx.x, ty = threadIdx.y;
    #pragma unroll
    for (int i = 0; i < 32; i += 8)
        t[ty + i][tx] = W[(size_t)(by + ty + i) * CDIM + bx + tx];
    __syncthreads();
    #pragma unroll
    for (int i = 0; i < 32; i += 8) {
        float v = t[tx][ty + i];
        size_t o = (size_t)(bx + ty + i) * CDIM + by + tx;
        __nv_bfloat16 hv = __float2bfloat16(v);
        Th[o] = hv;
        Tl[o] = __float2bfloat16(v - __bfloat162float(hv));
    }
}

// cp.async: rows x 64-elem tile (128B rows) into STRB-padded smem
__device__ __forceinline__ void cpa_tile(uint32_t dst, const void* gsrc, size_t rowStrideB, int rows, int tid) {
    const char* s = (const char*)gsrc;
    int total = rows * 8;
    for (int i = tid; i < total; i += 256) {
        int r = i >> 3, c = (i & 7) * 16;
        CPA16(dst + (uint32_t)(r * STRB + c), s + (size_t)r * rowStrideB + c);
    }
}

// ============ projections / out-proj: 128x128 tile, 3-pass bf16 ============
// mode 0: bf16 hi/lo head-major [h][s][d]; mode 1: transposed [n][m]; mode 2: fp32+bias
__global__ void __launch_bounds__(256) mma_gemm128(
    const __nv_bfloat16* __restrict__ Ah, const __nv_bfloat16* __restrict__ Al, int lda,
    const __nv_bfloat16* __restrict__ Bh, const __nv_bfloat16* __restrict__ Bl, int ldb,
    int kChunks, int mode,
    __nv_bfloat16* __restrict__ Oh, __nv_bfloat16* __restrict__ Ol,
    const float* __restrict__ bias, float* __restrict__ Ofp)
{
    extern __shared__ char smem[];
    uint32_t sb = smem_u32(smem);
    const uint32_t sAh = sb, sAl = sAh + TILEB, sBh = sAl + TILEB, sBl = sBh + TILEB;
    const int tid = threadIdx.x, wid = tid >> 5, lane = tid & 31;
    const int wr = wid >> 2, wc = wid & 3;
    const int g = lane >> 2, tig = lane & 3;
    const int mBase = blockIdx.y * 128, nBase = blockIdx.x * 128;

    float acc[4][4][4];
    #pragma unroll
    for (int i = 0; i < 4; i++)
        #pragma unroll
        for (int j = 0; j < 4; j++)
            #pragma unroll
            for (int k = 0; k < 4; k++) acc[i][j][k] = 0.f;

    const char* pAh = (const char*)(Ah + (size_t)mBase * lda);
    const char* pAl = (const char*)(Al + (size_t)mBase * lda);
    const char* pBh = (const char*)(Bh + (size_t)nBase * ldb);
    const char* pBl = (const char*)(Bl + (size_t)nBase * ldb);

    for (int ch = 0; ch < kChunks; ch++) {
        size_t kB = (size_t)ch * 128;   // 64 elems * 2B
        cpa_tile(sAh, pAh + kB, (size_t)lda * 2, 128, tid);
        cpa_tile(sAl, pAl + kB, (size_t)lda * 2, 128, tid);
        cpa_tile(sBh, pBh + kB, (size_t)ldb * 2, 128, tid);
        cpa_tile(sBl, pBl + kB, (size_t)ldb * 2, 128, tid);
        CP_COMMIT();
        CP_WAIT(0);
        __syncthreads();
        #pragma unroll
        for (int ks = 0; ks < 4; ks++) {
            uint32_t ah[4][4], al[4][4], bh[2][4], bl[2][4];
            #pragma unroll
            for (int fi = 0; fi < 4; fi++) {
                ldsm4(ldaddr(sAh, wr * 64 + fi * 16, STRB, ks * 32, lane), ah[fi]);
                ldsm4(ldaddr(sAl, wr * 64 + fi * 16, STRB, ks * 32, lane), al[fi]);
            }
            #pragma unroll
            for (int np = 0; np < 2; np++) {
                ldsm4(ldaddr(sBh, wc * 32 + np * 16, STRB, ks * 32, lane), bh[np]);
                ldsm4(ldaddr(sBl, wc * 32 + np * 16, STRB, ks * 32, lane), bl[np]);
            }
            #pragma unroll
            for (int fi = 0; fi < 4; fi++)
                #pragma unroll
                for (int np = 0; np < 2; np++) {
                    MMA(acc[fi][2 * np], ah[fi], bh[np][0], bh[np][2]);
                    MMA(acc[fi][2 * np], ah[fi], bl[np][0], bl[np][2]);
                    MMA(acc[fi][2 * np], al[fi], bh[np][0], bh[np][2]);
                    MMA(acc[fi][2 * np + 1], ah[fi], bh[np][1], bh[np][3]);
                    MMA(acc[fi][2 * np + 1], ah[fi], bl[np][1], bl[np][3]);
                    MMA(acc[fi][2 * np + 1], al[fi], bh[np][1], bh[np][3]);
                }
        }
        __syncthreads();
    }

    #pragma unroll
    for (int fi = 0; fi < 4; fi++) {
        #pragma unroll
        for (int fj = 0; fj < 4; fj++) {
            int m0 = mBase + wr * 64 + fi * 16 + g;
            int n0 = nBase + wc * 32 + fj * 8 + tig * 2;
            float c0 = acc[fi][fj][0], c1 = acc[fi][fj][1];
            float c2 = acc[fi][fj][2], c3 = acc[fi][fj][3];
            if (mode == 0) {
                int h = n0 >> 6, dd = n0 & 63;
                size_t o0 = ((size_t)h * SDIM + m0) * DHEAD + dd;
                size_t o1 = ((size_t)h * SDIM + m0 + 8) * DHEAD + dd;
                __nv_bfloat162 hv, lv;
                split2(c0, c1, hv, lv);
                *(__nv_bfloat162*)(Oh + o0) = hv; *(__nv_bfloat162*)(Ol + o0) = lv;
                split2(c2, c3, hv, lv);
                *(__nv_bfloat162*)(Oh + o1) = hv; *(__nv_bfloat162*)(Ol + o1) = lv;
            } else if (mode == 1) {
                size_t o00 = (size_t)n0 * SDIM + m0;
                size_t o01 = (size_t)(n0 + 1) * SDIM + m0;
                __nv_bfloat16 h0 = __float2bfloat16(c0);
                __nv_bfloat16 h1 = __float2bfloat16(c1);
                __nv_bfloat16 h2 = __float2bfloat16(c2);
                __nv_bfloat16 h3 = __float2bfloat16(c3);
                Oh[o00] = h0;     Ol[o00] = __float2bfloat16(c0 - __bfloat162float(h0));
                Oh[o01] = h1;     Ol[o01] = __float2bfloat16(c1 - __bfloat162float(h1));
                Oh[o00 + 8] = h2; Ol[o00 + 8] = __float2bfloat16(c2 - __bfloat162float(h2));
                Oh[o01 + 8] = h3; Ol[o01 + 8] = __float2bfloat16(c3 - __bfloat162float(h3));
            } else {
                float2 bv = *(const float2*)(bias + n0);
                *(float2*)(Ofp + (size_t)m0 * CDIM + n0) = make_float2(c0 + bv.x, c1 + bv.y);
                *(float2*)(Ofp + (size_t)(m0 + 8) * CDIM + n0) = make_float2(c2 + bv.x, c3 + bv.y);
            }
        }
    }
}

// ============ fused flash attention ============
// grid (18, 20); block 256 = 8 warps; warp owns 16 query rows; full 128-key N per warp.
// smem: Qh,Ql | Kh[2],Kl[2] | Vh[2],Vl[2] | Mask[2]  (double-buffered K/V/mask)
#define OQH 0
#define OQL 18432
#define OKH 36864
#define OKL 73728
#define OVH 110592
#define OVL 145408
#define OMK 180224
#define FLASH_SMEM 217088

__global__ void __launch_bounds__(256) flash_attn() {
    extern __shared__ char smem[];
    uint32_t sb = smem_u32(smem);
    const int tid = threadIdx.x, wid = tid >> 5, lane = tid & 31;
    const int g = lane >> 2, tig = lane & 3;
    const int qb = blockIdx.x, h = blockIdx.y;
    const int qBase = qb * 128;

    const char* gQh = (const char*)g_Qhi + ((size_t)h * SDIM + qBase) * 128;
    const char* gQl = (const char*)g_Qlo + ((size_t)h * SDIM + qBase) * 128;

    // preamble: Q + K/V/mask(kb=0) in group 0
    cpa_tile(sb + OQH, gQh, 128, 128, tid);
    cpa_tile(sb + OQL, gQl, 128, 128, tid);
    {
        int kb = 0, s = 0, kBase = 0;
        cpa_tile(sb + OKH + s * 18432, (const char*)g_Khi + ((size_t)h * SDIM + kBase) * 128, 128, 128, tid);
        cpa_tile(sb + OKL + s * 18432, (const char*)g_Klo + ((size_t)h * SDIM + kBase) * 128, 128, 128, tid);
        const char* gVh = (const char*)g_Vthi + ((size_t)(h * 64) * SDIM + kBase) * 2;
        const char* gVl = (const char*)g_Vtlo + ((size_t)(h * 64) * SDIM + kBase) * 2;
        for (int i = tid; i < 1024; i += 256) {
            int r = i >> 4, c = (i & 15) * 16;
            CPA16(sb + OVH + s * 17408 + (uint32_t)(r * LDVB + c), gVh + (size_t)r * (SDIM * 2) + c);
            CPA16(sb + OVL + s * 17408 + (uint32_t)(r * LDVB + c), gVl + (size_t)r * (SDIM * 2) + c);
        }
        cpa_tile(sb + OMK + s * 18432, g_mask + (size_t)qBase * SDIM + kBase, SDIM, 128, tid);
        (void)kb;
    }
    CP_COMMIT();

    float oacc[8][4];
    #pragma unroll
    for (int i = 0; i < 8; i++)
        #pragma unroll
        for (int k = 0; k < 4; k++) oacc[i][k] = 0.f;
    float m0 = -1e30f, m1 = -1e30f, l0 = 0.f, l1 = 0.f;
    const int r0l = wid * 16 + g;

    for (int kb = 0; kb < SDIM / 128; kb++) {
        if (kb + 1 < SDIM / 128) {
            int s = (kb + 1) & 1, kBase = (kb + 1) * 128;
            cpa_tile(sb + OKH + s * 18432, (const char*)g_Khi + ((size_t)h * SDIM + kBase) * 128, 128, 128, tid);
            cpa_tile(sb + OKL + s * 18432, (const char*)g_Klo + ((size_t)h * SDIM + kBase) * 128, 128, 128, tid);
            const char* gVh = (const char*)g_Vthi + ((size_t)(h * 64) * SDIM + kBase) * 2;
            const char* gVl = (const char*)g_Vtlo + ((size_t)(h * 64) * SDIM + kBase) * 2;
            for (int i = tid; i < 1024; i += 256) {
                int r = i >> 4, c = (i & 15) * 16;
                CPA16(sb + OVH + s * 17408 + (uint32_t)(r * LDVB + c), gVh + (size_t)r * (SDIM * 2) + c);
                CPA16(sb + OVL + s * 17408 + (uint32_t)(r * LDVB + c), gVl + (size_t)r * (SDIM * 2) + c);
            }
            cpa_tile(sb + OMK + s * 18432, g_mask + (size_t)qBase * SDIM + kBase, SDIM, 128, tid);
            CP_COMMIT();
            CP_WAIT(1);
        } else {
            CP_WAIT(0);
        }
        __syncthreads();

        const int s = kb & 1;
        const uint32_t bKh = sb + OKH + s * 18432, bKl = sb + OKL + s * 18432;
        const uint32_t bVh = sb + OVH + s * 17408, bVl = sb + OVL + s * 17408;
        const char* mkb = smem + OMK + s * 18432;

        // ---- S = Q K^T (3-pass) ----
        float sacc[16][4];
        #pragma unroll
        for (int i = 0; i < 16; i++)
            #pragma unroll
            for (int k = 0; k < 4; k++) sacc[i][k] = 0.f;
        #pragma unroll
        for (int ks = 0; ks < 4; ks++) {
            uint32_t aqh[4], aql[4];
            ldsm4(ldaddr(sb + OQH, wid * 16, STRB, ks * 32, lane), aqh);
            ldsm4(ldaddr(sb + OQL, wid * 16, STRB, ks * 32, lane), aql);
            #pragma unroll
            for (int np = 0; np < 8; np++) {
                uint32_t bh[4], bl[4];
                ldsm4(ldaddr(bKh, np * 16, STRB, ks * 32, lane), bh);
                ldsm4(ldaddr(bKl, np * 16, STRB, ks * 32, lane), bl);
                MMA(sacc[2 * np], aqh, bh[0], bh[2]);
                MMA(sacc[2 * np], aqh, bl[0], bl[2]);
                MMA(sacc[2 * np], aql, bh[0], bh[2]);
                MMA(sacc[2 * np + 1], aqh, bh[1], bh[3]);
                MMA(sacc[2 * np + 1], aqh, bl[1], bl[3]);
                MMA(sacc[2 * np + 1], aql, bh[1], bh[3]);
            }
        }

        // ---- scale + mask + online softmax ----
        float rmax0 = -1e30f, rmax1 = -1e30f;
        #pragma unroll
        for (int nf = 0; nf < 16; nf++) {
            int col = nf * 8 + tig * 2;
            uchar2 mk0 = *(const uchar2*)(mkb + r0l * STRB + col);
            uchar2 mk1 = *(const uchar2*)(mkb + (r0l + 8) * STRB + col);
            sacc[nf][0] = mk0.x ? sacc[nf][0] * 0.125f : -1e30f;
            sacc[nf][1] = mk0.y ? sacc[nf][1] * 0.125f : -1e30f;
            sacc[nf][2] = mk1.x ? sacc[nf][2] * 0.125f : -1e30f;
            sacc[nf][3] = mk1.y ? sacc[nf][3] * 0.125f : -1e30f;
            rmax0 = fmaxf(rmax0, fmaxf(sacc[nf][0], sacc[nf][1]));
            rmax1 = fmaxf(rmax1, fmaxf(sacc[nf][2], sacc[nf][3]));
        }
        rmax0 = fmaxf(rmax0, __shfl_xor_sync(0xffffffffu, rmax0, 1));
        rmax0 = fmaxf(rmax0, __shfl_xor_sync(0xffffffffu, rmax0, 2));
        rmax1 = fmaxf(rmax1, __shfl_xor_sync(0xffffffffu, rmax1, 1));
        rmax1 = fmaxf(rmax1, __shfl_xor_sync(0xffffffffu, rmax1, 2));
        float mn0 = fmaxf(m0, rmax0), mn1 = fmaxf(m1, rmax1);
        float al0 = __expf(m0 - mn0), al1 = __expf(m1 - mn1);
        m0 = mn0; m1 = mn1;
        float sum0 = 0.f, sum1 = 0.f;
        #pragma unroll
        for (int nf = 0; nf < 16; nf++) {
            sacc[nf][0] = __expf(sacc[nf][0] - mn0);
            sacc[nf][1] = __expf(sacc[nf][1] - mn0);
            sacc[nf][2] = __expf(sacc[nf][2] - mn1);
            sacc[nf][3] = __expf(sacc[nf][3] - mn1);
            sum0 += sacc[nf][0] + sacc[nf][1];
            sum1 += sacc[nf][2] + sacc[nf][3];
        }
        sum0 += __shfl_xor_sync(0xffffffffu, sum0, 1);
        sum0 += __shfl_xor_sync(0xffffffffu, sum0, 2);
        sum1 += __shfl_xor_sync(0xffffffffu, sum1, 1);
        sum1 += __shfl_xor_sync(0xffffffffu, sum1, 2);
        l0 = l0 * al0 + sum0;
        l1 = l1 * al1 + sum1;
        #pragma unroll
        for (int nf = 0; nf < 8; nf++) {
            oacc[nf][0] *= al0; oacc[nf][1] *= al0;
            oacc[nf][2] *= al1; oacc[nf][3] *= al1;
        }

        // ---- pack P (hi/lo) into A-operand fragments ----
        uint32_t ph[8][4], pl[8][4];
        #pragma unroll
        for (int kc = 0; kc < 8; kc++) {
            float x0 = sacc[2 * kc][0], x1 = sacc[2 * kc][1];
            float x2 = sacc[2 * kc][2], x3 = sacc[2 * kc][3];
            float y0 = sacc[2 * kc + 1][0], y1 = sacc[2 * kc + 1][1];
            float y2 = sacc[2 * kc + 1][2], y3 = sacc[2 * kc + 1][3];
            __nv_bfloat162 hv, lv;
            split2(x0, x1, hv, lv); ph[kc][0] = *(uint32_t*)&hv; pl[kc][0] = *(uint32_t*)&lv;
            split2(x2, x3, hv, lv); ph[kc][1] = *(uint32_t*)&hv; pl[kc][1] = *(uint32_t*)&lv;
            split2(y0, y1, hv, lv); ph[kc][2] = *(uint32_t*)&hv; pl[kc][2] = *(uint32_t*)&lv;
            split2(y2, y3, hv, lv); ph[kc][3] = *(uint32_t*)&hv; pl[kc][3] = *(uint32_t*)&lv;
        }

        // ---- O += P @ V (3-pass) ----
        #pragma unroll
        for (int kc = 0; kc < 8; kc++) {
            #pragma unroll
            for (int np = 0; np < 4; np++) {
                uint32_t vh[4], vl[4];
                ldsm4(ldaddr(bVh, np * 16, LDVB, kc * 32, lane), vh);
                ldsm4(ldaddr(bVl, np * 16, LDVB, kc * 32, lane), vl);
                MMA(oacc[2 * np], ph[kc], vh[0], vh[2]);
                MMA(oacc[2 * np], ph[kc], vl[0], vl[2]);
                MMA(oacc[2 * np], pl[kc], vh[0], vh[2]);
                MMA(oacc[2 * np + 1], ph[kc], vh[1], vh[3]);
                MMA(oacc[2 * np + 1], ph[kc], vl[1], vl[3]);
                MMA(oacc[2 * np + 1], pl[kc], vh[1], vh[3]);
            }
        }
        __syncthreads();
    }

    // ---- epilogue: O /= l, write Ctx hi/lo ----
    float inv0 = 1.f / l0, inv1 = 1.f / l1;
    int mrow = qBase + r0l;
    #pragma unroll
    for (int nf = 0; nf < 8; nf++) {
        int col = h * 64 + nf * 8 + tig * 2;
        __nv_bfloat162 hv, lv;
        split2(oacc[nf][0] * inv0, oacc[nf][1] * inv0, hv, lv);
        *(__nv_bfloat162*)(g_Ch + (size_t)mrow * CDIM + col) = hv;
        *(__nv_bfloat162*)(g_Cl + (size_t)mrow * CDIM + col) = lv;
        split2(oacc[nf][2] * inv1, oacc[nf][3] * inv1, hv, lv);
        *(__nv_bfloat162*)(g_Ch + (size_t)(mrow + 8) * CDIM + col) = hv;
        *(__nv_bfloat162*)(g_Cl + (size_t)(mrow + 8) * CDIM + col) = lv;
    }
}

// ---------------- launcher ----------------
extern "C" void kernel_launch(void* const* d_in, const int* in_sizes, int n_in,
                              void* d_out, int out_size) {
    const float* hidden = (const float*)d_in[0];
    const void*  mask   = d_in[1];
    const float* Wq     = (const float*)d_in[2];
    const float* Wk     = (const float*)d_in[3];
    const float* Wv     = (const float*)d_in[4];
    const float* Wo     = (const float*)d_in[5];
    const float* bo     = (const float*)d_in[6];
    float* out = (float*)d_out;

    __nv_bfloat16 *xh, *xl, *wqh, *wql, *wkh, *wkl, *wvh, *wvl, *woh, *wol;
    __nv_bfloat16 *qh, *ql, *kh, *kl, *vth, *vtl, *chh, *cll;
    cudaGetSymbolAddress((void**)&xh,  g_Xhi);  cudaGetSymbolAddress((void**)&xl,  g_Xlo);
    cudaGetSymbolAddress((void**)&wqh, g_Wqh);  cudaGetSymbolAddress((void**)&wql, g_Wql);
    cudaGetSymbolAddress((void**)&wkh, g_Wkh);  cudaGetSymbolAddress((void**)&wkl, g_Wkl);
    cudaGetSymbolAddress((void**)&wvh, g_Wvh);  cudaGetSymbolAddress((void**)&wvl, g_Wvl);
    cudaGetSymbolAddress((void**)&woh, g_Woh);  cudaGetSymbolAddress((void**)&wol, g_Wol);
    cudaGetSymbolAddress((void**)&qh,  g_Qhi);  cudaGetSymbolAddress((void**)&ql,  g_Qlo);
    cudaGetSymbolAddress((void**)&kh,  g_Khi);  cudaGetSymbolAddress((void**)&kl,  g_Klo);
    cudaGetSymbolAddress((void**)&vth, g_Vthi); cudaGetSymbolAddress((void**)&vtl, g_Vtlo);
    cudaGetSymbolAddress((void**)&chh, g_Ch);   cudaGetSymbolAddress((void**)&cll, g_Cl);

    const int smemBig = 4 * TILEB;   // 73728
    cudaFuncSetAttribute(mma_gemm128, cudaFuncAttributeMaxDynamicSharedMemorySize, smemBig);
    cudaFuncSetAttribute(flash_attn,  cudaFuncAttributeMaxDynamicSharedMemorySize, FLASH_SMEM);

    // preprocessing
    detect_mask_kernel<<<1, 32>>>((const unsigned int*)mask);
    norm_mask_kernel<<<(int)((SS + 255) / 256), 256>>>(mask);
    conv_x_kernel<<<(int)(((size_t)SDIM * CDIM / 2 + 255) / 256), 256>>>(hidden);
    dim3 tb(32, 8), tg(CDIM / 32, CDIM / 32);
    transpose_w_kernel<<<tg, tb>>>(Wq, wqh, wql);
    transpose_w_kernel<<<tg, tb>>>(Wk, wkh, wkl);
    transpose_w_kernel<<<tg, tb>>>(Wv, wvh, wvl);
    transpose_w_kernel<<<tg, tb>>>(Wo, woh, wol);

    // projections
    dim3 gProj(CDIM / 128, SDIM / 128);
    mma_gemm128<<<gProj, 256, smemBig>>>(xh, xl, CDIM, wqh, wql, CDIM, CDIM / 64, 0, qh, ql, nullptr, nullptr);
    mma_gemm128<<<gProj, 256, smemBig>>>(xh, xl, CDIM, wkh, wkl, CDIM, CDIM / 64, 0, kh, kl, nullptr, nullptr);
    mma_gemm128<<<gProj, 256, smemBig>>>(xh, xl, CDIM, wvh, wvl, CDIM, CDIM / 64, 1, vth, vtl, nullptr, nullptr);

    // fused attention
    dim3 gF(SDIM / 128, NHEAD);
    flash_attn<<<gF, 256, FLASH_SMEM>>>();

    // output projection
    dim3 gOut(CDIM / 128, SDIM / 128);
    mma_gemm128<<<gOut, 256, smemBig>>>(chh, cll, CDIM, woh, wol, CDIM, CDIM / 64, 2, nullptr, nullptr, bo, out);
}

// round 5
// speedup vs baseline: 2.6604x; 1.0005x over previous
#include <cuda_runtime.h>
#include <cuda_bf16.h>
#include <cstdint>

#define SDIM 2304
#define CDIM 1280
#define NHEAD 20
#define DHEAD 64
#define SS ((size_t)SDIM * SDIM)
#define LDK 72                       // padded row stride (elems) for 64-wide tiles: 144B
#define STRB 144
#define LDVB 272                     // V^T tile row stride bytes (128 keys*2B + 16 pad)
#define TILEB (128 * STRB)           // 18432

// ---------------- static scratch ----------------
__device__ __align__(256) __nv_bfloat16 g_Qhi[(size_t)NHEAD * SDIM * DHEAD];
__device__ __align__(256) __nv_bfloat16 g_Qlo[(size_t)NHEAD * SDIM * DHEAD];
__device__ __align__(256) __nv_bfloat16 g_Khi[(size_t)NHEAD * SDIM * DHEAD];
__device__ __align__(256) __nv_bfloat16 g_Klo[(size_t)NHEAD * SDIM * DHEAD];
__device__ __align__(256) __nv_bfloat16 g_Vthi[(size_t)CDIM * SDIM];   // [h*64+d][s]
__device__ __align__(256) __nv_bfloat16 g_Vtlo[(size_t)CDIM * SDIM];
__device__ __align__(256) __nv_bfloat16 g_Xhi[(size_t)SDIM * CDIM];
__device__ __align__(256) __nv_bfloat16 g_Xlo[(size_t)SDIM * CDIM];
__device__ __align__(256) __nv_bfloat16 g_Wqh[(size_t)CDIM * CDIM];    // W^T [n][k]
__device__ __align__(256) __nv_bfloat16 g_Wql[(size_t)CDIM * CDIM];
__device__ __align__(256) __nv_bfloat16 g_Wkh[(size_t)CDIM * CDIM];
__device__ __align__(256) __nv_bfloat16 g_Wkl[(size_t)CDIM * CDIM];
__device__ __align__(256) __nv_bfloat16 g_Wvh[(size_t)CDIM * CDIM];
__device__ __align__(256) __nv_bfloat16 g_Wvl[(size_t)CDIM * CDIM];
__device__ __align__(256) __nv_bfloat16 g_Woh[(size_t)CDIM * CDIM];
__device__ __align__(256) __nv_bfloat16 g_Wol[(size_t)CDIM * CDIM];
__device__ __align__(256) __nv_bfloat16 g_Ch[(size_t)SDIM * CDIM];
__device__ __align__(256) __nv_bfloat16 g_Cl[(size_t)SDIM * CDIM];
__device__ __align__(256) unsigned char g_mask[SS];
__device__ int g_mask_mode;

// ---------------- helpers ----------------
__device__ __forceinline__ uint32_t smem_u32(const void* p) {
    uint32_t a;
    asm("{ .reg .u64 t; cvta.to.shared.u64 t, %1; cvt.u32.u64 %0, t; }" : "=r"(a) : "l"(p));
    return a;
}
#define CPA16(dst, src) asm volatile("cp.async.cg.shared.global [%0], [%1], 16;" :: "r"(dst), "l"(src))
#define CP_COMMIT()     asm volatile("cp.async.commit_group;" ::: "memory")
#define CP_WAIT(n)      asm volatile("cp.async.wait_group %0;" :: "n"(n) : "memory")

__device__ __forceinline__ void ldsm4(uint32_t addr, uint32_t r[4]) {
    asm volatile("ldmatrix.sync.aligned.m8n8.x4.shared.b16 {%0,%1,%2,%3},[%4];"
        : "=r"(r[0]), "=r"(r[1]), "=r"(r[2]), "=r"(r[3]) : "r"(addr));
}
// base + row-block rbase, 16 rows via lane&15, k-halves via lane>>4
__device__ __forceinline__ uint32_t ldaddr(uint32_t base, int rbase, int strideB, int kByte, int lane) {
    return base + (uint32_t)((rbase + (lane & 15)) * strideB + kByte + ((lane >> 4) << 4));
}
__device__ __forceinline__ void MMA(float c[4], const uint32_t a[4], uint32_t b0, uint32_t b1) {
    asm volatile(
        "mma.sync.aligned.m16n8k16.row.col.f32.bf16.bf16.f32 "
        "{%0,%1,%2,%3},{%4,%5,%6,%7},{%8,%9},{%0,%1,%2,%3};"
        : "+f"(c[0]), "+f"(c[1]), "+f"(c[2]), "+f"(c[3])
        : "r"(a[0]), "r"(a[1]), "r"(a[2]), "r"(a[3]), "r"(b0), "r"(b1));
}
__device__ __forceinline__ uint32_t packbf2(float x, float y) {
    __nv_bfloat162 t = __floats2bfloat162_rn(x, y);
    return *(uint32_t*)&t;
}
__device__ __forceinline__ void split2(float a, float b, __nv_bfloat162& hi, __nv_bfloat162& lo) {
    __nv_bfloat16 ha = __float2bfloat16(a), hb = __float2bfloat16(b);
    hi = __halves2bfloat162(ha, hb);
    lo = __halves2bfloat162(__float2bfloat16(a - __bfloat162float(ha)),
                            __float2bfloat16(b - __bfloat162float(hb)));
}

// ---------------- mask detect/normalize ----------------
__global__ void detect_mask_kernel(const unsigned int* __restrict__ m) {
    if (threadIdx.x != 0) return;
    bool all01 = true, allf = true;
    #pragma unroll 1
    for (int i = 0; i < 256; i++) {
        unsigned int w = m[i * 997 + 1];
        if (!(w == 0u || w == 1u)) all01 = false;
        if (!(w == 0u || w == 0x3F800000u)) allf = false;
    }
    g_mask_mode = (all01 || allf) ? 1 : 2;
}
__global__ void norm_mask_kernel(const void* __restrict__ m) {
    size_t i = (size_t)blockIdx.x * 256 + threadIdx.x;
    if (i >= SS) return;
    if (g_mask_mode == 1) g_mask[i] = (((const unsigned int*)m)[i] != 0u) ? 1 : 0;
    else                  g_mask[i] = (((const unsigned char*)m)[i] != 0) ? 1 : 0;
}

// ---------------- preprocessing ----------------
__global__ void conv_x_kernel(const float* __restrict__ X) {
    size_t i = (size_t)blockIdx.x * 256 + threadIdx.x;
    if (i >= (size_t)SDIM * CDIM / 2) return;
    float2 v = *(const float2*)(X + 2 * i);
    __nv_bfloat162 h, l;
    split2(v.x, v.y, h, l);
    *(__nv_bfloat162*)(g_Xhi + 2 * i) = h;
    *(__nv_bfloat162*)(g_Xlo + 2 * i) = l;
}
__global__ void transpose_w_kernel(const float* __restrict__ W,
                                   __nv_bfloat16* __restrict__ Th, __nv_bfloat16* __restrict__ Tl) {
    __shared__ float t[32][33];
    int bx = blockIdx.x * 32, by = blockIdx.y * 32;
    int tx = threadIdx.x, ty = threadIdx.y;
    #pragma unroll
    for (int i = 0; i < 32; i += 8)
        t[ty + i][tx] = W[(size_t)(by + ty + i) * CDIM + bx + tx];
    __syncthreads();
    #pragma unroll
    for (int i = 0; i < 32; i += 8) {
        float v = t[tx][ty + i];
        size_t o = (size_t)(bx + ty + i) * CDIM + by + tx;
        __nv_bfloat16 hv = __float2bfloat16(v);
        Th[o] = hv;
        Tl[o] = __float2bfloat16(v - __bfloat162float(hv));
    }
}

// cp.async: rows x 64-elem tile (128B rows) into STRB-padded smem
__device__ __forceinline__ void cpa_tile(uint32_t dst, const void* gsrc, size_t rowStrideB, int rows, int tid) {
    const char* s = (const char*)gsrc;
    int total = rows * 8;
    for (int i = tid; i < total; i += 256) {
        int r = i >> 3, c = (i & 7) * 16;
        CPA16(dst + (uint32_t)(r * STRB + c), s + (size_t)r * rowStrideB + c);
    }
}

// ============ projections / out-proj: 128x128 tile, 3-pass bf16 ============
// mode 0: bf16 hi/lo head-major [h][s][d]; mode 1: transposed [n][m]; mode 2: fp32+bias
__global__ void __launch_bounds__(256) mma_gemm128(
    const __nv_bfloat16* __restrict__ Ah, const __nv_bfloat16* __restrict__ Al, int lda,
    const __nv_bfloat16* __restrict__ Bh, const __nv_bfloat16* __restrict__ Bl, int ldb,
    int kChunks, int mode,
    __nv_bfloat16* __restrict__ Oh, __nv_bfloat16* __restrict__ Ol,
    const float* __restrict__ bias, float* __restrict__ Ofp)
{
    extern __shared__ char smem[];
    uint32_t sb = smem_u32(smem);
    const uint32_t sAh = sb, sAl = sAh + TILEB, sBh = sAl + TILEB, sBl = sBh + TILEB;
    const int tid = threadIdx.x, wid = tid >> 5, lane = tid & 31;
    const int wr = wid >> 2, wc = wid & 3;
    const int g = lane >> 2, tig = lane & 3;
    const int mBase = blockIdx.y * 128, nBase = blockIdx.x * 128;

    float acc[4][4][4];
    #pragma unroll
    for (int i = 0; i < 4; i++)
        #pragma unroll
        for (int j = 0; j < 4; j++)
            #pragma unroll
            for (int k = 0; k < 4; k++) acc[i][j][k] = 0.f;

    const char* pAh = (const char*)(Ah + (size_t)mBase * lda);
    const char* pAl = (const char*)(Al + (size_t)mBase * lda);
    const char* pBh = (const char*)(Bh + (size_t)nBase * ldb);
    const char* pBl = (const char*)(Bl + (size_t)nBase * ldb);

    for (int ch = 0; ch < kChunks; ch++) {
        size_t kB = (size_t)ch * 128;   // 64 elems * 2B
        cpa_tile(sAh, pAh + kB, (size_t)lda * 2, 128, tid);
        cpa_tile(sAl, pAl + kB, (size_t)lda * 2, 128, tid);
        cpa_tile(sBh, pBh + kB, (size_t)ldb * 2, 128, tid);
        cpa_tile(sBl, pBl + kB, (size_t)ldb * 2, 128, tid);
        CP_COMMIT();
        CP_WAIT(0);
        __syncthreads();
        #pragma unroll
        for (int ks = 0; ks < 4; ks++) {
            uint32_t ah[4][4], al[4][4], bh[2][4], bl[2][4];
            #pragma unroll
            for (int fi = 0; fi < 4; fi++) {
                ldsm4(ldaddr(sAh, wr * 64 + fi * 16, STRB, ks * 32, lane), ah[fi]);
                ldsm4(ldaddr(sAl, wr * 64 + fi * 16, STRB, ks * 32, lane), al[fi]);
            }
            #pragma unroll
            for (int np = 0; np < 2; np++) {
                ldsm4(ldaddr(sBh, wc * 32 + np * 16, STRB, ks * 32, lane), bh[np]);
                ldsm4(ldaddr(sBl, wc * 32 + np * 16, STRB, ks * 32, lane), bl[np]);
            }
            #pragma unroll
            for (int fi = 0; fi < 4; fi++)
                #pragma unroll
                for (int np = 0; np < 2; np++) {
                    MMA(acc[fi][2 * np], ah[fi], bh[np][0], bh[np][2]);
                    MMA(acc[fi][2 * np], ah[fi], bl[np][0], bl[np][2]);
                    MMA(acc[fi][2 * np], al[fi], bh[np][0], bh[np][2]);
                    MMA(acc[fi][2 * np + 1], ah[fi], bh[np][1], bh[np][3]);
                    MMA(acc[fi][2 * np + 1], ah[fi], bl[np][1], bl[np][3]);
                    MMA(acc[fi][2 * np + 1], al[fi], bh[np][1], bh[np][3]);
                }
        }
        __syncthreads();
    }

    #pragma unroll
    for (int fi = 0; fi < 4; fi++) {
        #pragma unroll
        for (int fj = 0; fj < 4; fj++) {
            int m0 = mBase + wr * 64 + fi * 16 + g;
            int n0 = nBase + wc * 32 + fj * 8 + tig * 2;
            float c0 = acc[fi][fj][0], c1 = acc[fi][fj][1];
            float c2 = acc[fi][fj][2], c3 = acc[fi][fj][3];
            if (mode == 0) {
                int h = n0 >> 6, dd = n0 & 63;
                size_t o0 = ((size_t)h * SDIM + m0) * DHEAD + dd;
                size_t o1 = ((size_t)h * SDIM + m0 + 8) * DHEAD + dd;
                __nv_bfloat162 hv, lv;
                split2(c0, c1, hv, lv);
                *(__nv_bfloat162*)(Oh + o0) = hv; *(__nv_bfloat162*)(Ol + o0) = lv;
                split2(c2, c3, hv, lv);
                *(__nv_bfloat162*)(Oh + o1) = hv; *(__nv_bfloat162*)(Ol + o1) = lv;
            } else if (mode == 1) {
                size_t o00 = (size_t)n0 * SDIM + m0;
                size_t o01 = (size_t)(n0 + 1) * SDIM + m0;
                __nv_bfloat16 h0 = __float2bfloat16(c0);
                __nv_bfloat16 h1 = __float2bfloat16(c1);
                __nv_bfloat16 h2 = __float2bfloat16(c2);
                __nv_bfloat16 h3 = __float2bfloat16(c3);
                Oh[o00] = h0;     Ol[o00] = __float2bfloat16(c0 - __bfloat162float(h0));
                Oh[o01] = h1;     Ol[o01] = __float2bfloat16(c1 - __bfloat162float(h1));
                Oh[o00 + 8] = h2; Ol[o00 + 8] = __float2bfloat16(c2 - __bfloat162float(h2));
                Oh[o01 + 8] = h3; Ol[o01 + 8] = __float2bfloat16(c3 - __bfloat162float(h3));
            } else {
                float2 bv = *(const float2*)(bias + n0);
                *(float2*)(Ofp + (size_t)m0 * CDIM + n0) = make_float2(c0 + bv.x, c1 + bv.y);
                *(float2*)(Ofp + (size_t)(m0 + 8) * CDIM + n0) = make_float2(c2 + bv.x, c3 + bv.y);
            }
        }
    }
}

// ============ fused flash attention ============
// grid (18, 20); block 256 = 8 warps; warp owns 16 query rows; full 128-key N per warp.
// smem: Qh,Ql | Kh[2],Kl[2] | Vh[2],Vl[2] | Mask[2]  (double-buffered K/V/mask)
#define OQH 0
#define OQL 18432
#define OKH 36864
#define OKL 73728
#define OVH 110592
#define OVL 145408
#define OMK 180224
#define FLASH_SMEM 217088

__global__ void __launch_bounds__(256) flash_attn() {
    extern __shared__ char smem[];
    uint32_t sb = smem_u32(smem);
    const int tid = threadIdx.x, wid = tid >> 5, lane = tid & 31;
    const int g = lane >> 2, tig = lane & 3;
    const int qb = blockIdx.x, h = blockIdx.y;
    const int qBase = qb * 128;

    const char* gQh = (const char*)g_Qhi + ((size_t)h * SDIM + qBase) * 128;
    const char* gQl = (const char*)g_Qlo + ((size_t)h * SDIM + qBase) * 128;

    // preamble: Q + K/V/mask(kb=0) in group 0
    cpa_tile(sb + OQH, gQh, 128, 128, tid);
    cpa_tile(sb + OQL, gQl, 128, 128, tid);
    {
        int kb = 0, s = 0, kBase = 0;
        cpa_tile(sb + OKH + s * 18432, (const char*)g_Khi + ((size_t)h * SDIM + kBase) * 128, 128, 128, tid);
        cpa_tile(sb + OKL + s * 18432, (const char*)g_Klo + ((size_t)h * SDIM + kBase) * 128, 128, 128, tid);
        const char* gVh = (const char*)g_Vthi + ((size_t)(h * 64) * SDIM + kBase) * 2;
        const char* gVl = (const char*)g_Vtlo + ((size_t)(h * 64) * SDIM + kBase) * 2;
        for (int i = tid; i < 1024; i += 256) {
            int r = i >> 4, c = (i & 15) * 16;
            CPA16(sb + OVH + s * 17408 + (uint32_t)(r * LDVB + c), gVh + (size_t)r * (SDIM * 2) + c);
            CPA16(sb + OVL + s * 17408 + (uint32_t)(r * LDVB + c), gVl + (size_t)r * (SDIM * 2) + c);
        }
        cpa_tile(sb + OMK + s * 18432, g_mask + (size_t)qBase * SDIM + kBase, SDIM, 128, tid);
        (void)kb;
    }
    CP_COMMIT();

    float oacc[8][4];
    #pragma unroll
    for (int i = 0; i < 8; i++)
        #pragma unroll
        for (int k = 0; k < 4; k++) oacc[i][k] = 0.f;
    float m0 = -1e30f, m1 = -1e30f, l0 = 0.f, l1 = 0.f;
    const int r0l = wid * 16 + g;

    for (int kb = 0; kb < SDIM / 128; kb++) {
        if (kb + 1 < SDIM / 128) {
            int s = (kb + 1) & 1, kBase = (kb + 1) * 128;
            cpa_tile(sb + OKH + s * 18432, (const char*)g_Khi + ((size_t)h * SDIM + kBase) * 128, 128, 128, tid);
            cpa_tile(sb + OKL + s * 18432, (const char*)g_Klo + ((size_t)h * SDIM + kBase) * 128, 128, 128, tid);
            const char* gVh = (const char*)g_Vthi + ((size_t)(h * 64) * SDIM + kBase) * 2;
            const char* gVl = (const char*)g_Vtlo + ((size_t)(h * 64) * SDIM + kBase) * 2;
            for (int i = tid; i < 1024; i += 256) {
                int r = i >> 4, c = (i & 15) * 16;
                CPA16(sb + OVH + s * 17408 + (uint32_t)(r * LDVB + c), gVh + (size_t)r * (SDIM * 2) + c);
                CPA16(sb + OVL + s * 17408 + (uint32_t)(r * LDVB + c), gVl + (size_t)r * (SDIM * 2) + c);
            }
            cpa_tile(sb + OMK + s * 18432, g_mask + (size_t)qBase * SDIM + kBase, SDIM, 128, tid);
            CP_COMMIT();
            CP_WAIT(1);
        } else {
            CP_WAIT(0);
        }
        __syncthreads();

        const int s = kb & 1;
        const uint32_t bKh = sb + OKH + s * 18432, bKl = sb + OKL + s * 18432;
        const uint32_t bVh = sb + OVH + s * 17408, bVl = sb + OVL + s * 17408;
        const char* mkb = smem + OMK + s * 18432;

        // ---- S = Q K^T (3-pass) ----
        float sacc[16][4];
        #pragma unroll
        for (int i = 0; i < 16; i++)
            #pragma unroll
            for (int k = 0; k < 4; k++) sacc[i][k] = 0.f;
        #pragma unroll
        for (int ks = 0; ks < 4; ks++) {
            uint32_t aqh[4], aql[4];
            ldsm4(ldaddr(sb + OQH, wid * 16, STRB, ks * 32, lane), aqh);
            ldsm4(ldaddr(sb + OQL, wid * 16, STRB, ks * 32, lane), aql);
            #pragma unroll
            for (int np = 0; np < 8; np++) {
                uint32_t bh[4], bl[4];
                ldsm4(ldaddr(bKh, np * 16, STRB, ks * 32, lane), bh);
                ldsm4(ldaddr(bKl, np * 16, STRB, ks * 32, lane), bl);
                MMA(sacc[2 * np], aqh, bh[0], bh[2]);
                MMA(sacc[2 * np], aqh, bl[0], bl[2]);
                MMA(sacc[2 * np], aql, bh[0], bh[2]);
                MMA(sacc[2 * np + 1], aqh, bh[1], bh[3]);
                MMA(sacc[2 * np + 1], aqh, bl[1], bl[3]);
                MMA(sacc[2 * np + 1], aql, bh[1], bh[3]);
            }
        }

        // ---- scale + mask + online softmax ----
        float rmax0 = -1e30f, rmax1 = -1e30f;
        #pragma unroll
        for (int nf = 0; nf < 16; nf++) {
            int col = nf * 8 + tig * 2;
            uchar2 mk0 = *(const uchar2*)(mkb + r0l * STRB + col);
            uchar2 mk1 = *(const uchar2*)(mkb + (r0l + 8) * STRB + col);
            sacc[nf][0] = mk0.x ? sacc[nf][0] * 0.125f : -1e30f;
            sacc[nf][1] = mk0.y ? sacc[nf][1] * 0.125f : -1e30f;
            sacc[nf][2] = mk1.x ? sacc[nf][2] * 0.125f : -1e30f;
            sacc[nf][3] = mk1.y ? sacc[nf][3] * 0.125f : -1e30f;
            rmax0 = fmaxf(rmax0, fmaxf(sacc[nf][0], sacc[nf][1]));
            rmax1 = fmaxf(rmax1, fmaxf(sacc[nf][2], sacc[nf][3]));
        }
        rmax0 = fmaxf(rmax0, __shfl_xor_sync(0xffffffffu, rmax0, 1));
        rmax0 = fmaxf(rmax0, __shfl_xor_sync(0xffffffffu, rmax0, 2));
        rmax1 = fmaxf(rmax1, __shfl_xor_sync(0xffffffffu, rmax1, 1));
        rmax1 = fmaxf(rmax1, __shfl_xor_sync(0xffffffffu, rmax1, 2));
        float mn0 = fmaxf(m0, rmax0), mn1 = fmaxf(m1, rmax1);
        float al0 = __expf(m0 - mn0), al1 = __expf(m1 - mn1);
        m0 = mn0; m1 = mn1;
        float sum0 = 0.f, sum1 = 0.f;
        #pragma unroll
        for (int nf = 0; nf < 16; nf++) {
            sacc[nf][0] = __expf(sacc[nf][0] - mn0);
            sacc[nf][1] = __expf(sacc[nf][1] - mn0);
            sacc[nf][2] = __expf(sacc[nf][2] - mn1);
            sacc[nf][3] = __expf(sacc[nf][3] - mn1);
            sum0 += sacc[nf][0] + sacc[nf][1];
            sum1 += sacc[nf][2] + sacc[nf][3];
        }
        sum0 += __shfl_xor_sync(0xffffffffu, sum0, 1);
        sum0 += __shfl_xor_sync(0xffffffffu, sum0, 2);
        sum1 += __shfl_xor_sync(0xffffffffu, sum1, 1);
        sum1 += __shfl_xor_sync(0xffffffffu, sum1, 2);
        l0 = l0 * al0 + sum0;
        l1 = l1 * al1 + sum1;
        #pragma unroll
        for (int nf = 0; nf < 8; nf++) {
            oacc[nf][0] *= al0; oacc[nf][1] *= al0;
            oacc[nf][2] *= al1; oacc[nf][3] *= al1;
        }

        // ---- pack P (hi/lo) into A-operand fragments ----
        uint32_t ph[8][4], pl[8][4];
        #pragma unroll
        for (int kc = 0; kc < 8; kc++) {
            float x0 = sacc[2 * kc][0], x1 = sacc[2 * kc][1];
            float x2 = sacc[2 * kc][2], x3 = sacc[2 * kc][3];
            float y0 = sacc[2 * kc + 1][0], y1 = sacc[2 * kc + 1][1];
            float y2 = sacc[2 * kc + 1][2], y3 = sacc[2 * kc + 1][3];
            __nv_bfloat162 hv, lv;
            split2(x0, x1, hv, lv); ph[kc][0] = *(uint32_t*)&hv; pl[kc][0] = *(uint32_t*)&lv;
            split2(x2, x3, hv, lv); ph[kc][1] = *(uint32_t*)&hv; pl[kc][1] = *(uint32_t*)&lv;
            split2(y0, y1, hv, lv); ph[kc][2] = *(uint32_t*)&hv; pl[kc][2] = *(uint32_t*)&lv;
            split2(y2, y3, hv, lv); ph[kc][3] = *(uint32_t*)&hv; pl[kc][3] = *(uint32_t*)&lv;
        }

        // ---- O += P @ V (3-pass) ----
        #pragma unroll
        for (int kc = 0; kc < 8; kc++) {
            #pragma unroll
            for (int np = 0; np < 4; np++) {
                uint32_t vh[4], vl[4];
                ldsm4(ldaddr(bVh, np * 16, LDVB, kc * 32, lane), vh);
                ldsm4(ldaddr(bVl, np * 16, LDVB, kc * 32, lane), vl);
                MMA(oacc[2 * np], ph[kc], vh[0], vh[2]);
                MMA(oacc[2 * np], ph[kc], vl[0], vl[2]);
                MMA(oacc[2 * np], pl[kc], vh[0], vh[2]);
                MMA(oacc[2 * np + 1], ph[kc], vh[1], vh[3]);
                MMA(oacc[2 * np + 1], ph[kc], vl[1], vl[3]);
                MMA(oacc[2 * np + 1], pl[kc], vh[1], vh[3]);
            }
        }
        __syncthreads();
    }

    // ---- epilogue: O /= l, write Ctx hi/lo ----
    float inv0 = 1.f / l0, inv1 = 1.f / l1;
    int mrow = qBase + r0l;
    #pragma unroll
    for (int nf = 0; nf < 8; nf++) {
        int col = h * 64 + nf * 8 + tig * 2;
        __nv_bfloat162 hv, lv;
        split2(oacc[nf][0] * inv0, oacc[nf][1] * inv0, hv, lv);
        *(__nv_bfloat162*)(g_Ch + (size_t)mrow * CDIM + col) = hv;
        *(__nv_bfloat162*)(g_Cl + (size_t)mrow * CDIM + col) = lv;
        split2(oacc[nf][2] * inv1, oacc[nf][3] * inv1, hv, lv);
        *(__nv_bfloat162*)(g_Ch + (size_t)(mrow + 8) * CDIM + col) = hv;
        *(__nv_bfloat162*)(g_Cl + (size_t)(mrow + 8) * CDIM + col) = lv;
    }
}

// ---------------- launcher ----------------
extern "C" void kernel_launch(void* const* d_in, const int* in_sizes, int n_in,
                              void* d_out, int out_size) {
    const float* hidden = (const float*)d_in[0];
    const void*  mask   = d_in[1];
    const float* Wq     = (const float*)d_in[2];
    const float* Wk     = (const float*)d_in[3];
    const float* Wv     = (const float*)d_in[4];
    const float* Wo     = (const float*)d_in[5];
    const float* bo     = (const float*)d_in[6];
    float* out = (float*)d_out;

    __nv_bfloat16 *xh, *xl, *wqh, *wql, *wkh, *wkl, *wvh, *wvl, *woh, *wol;
    __nv_bfloat16 *qh, *ql, *kh, *kl, *vth, *vtl, *chh, *cll;
    cudaGetSymbolAddress((void**)&xh,  g_Xhi);  cudaGetSymbolAddress((void**)&xl,  g_Xlo);
    cudaGetSymbolAddress((void**)&wqh, g_Wqh);  cudaGetSymbolAddress((void**)&wql, g_Wql);
    cudaGetSymbolAddress((void**)&wkh, g_Wkh);  cudaGetSymbolAddress((void**)&wkl, g_Wkl);
    cudaGetSymbolAddress((void**)&wvh, g_Wvh);  cudaGetSymbolAddress((void**)&wvl, g_Wvl);
    cudaGetSymbolAddress((void**)&woh, g_Woh);  cudaGetSymbolAddress((void**)&wol, g_Wol);
    cudaGetSymbolAddress((void**)&qh,  g_Qhi);  cudaGetSymbolAddress((void**)&ql,  g_Qlo);
    cudaGetSymbolAddress((void**)&kh,  g_Khi);  cudaGetSymbolAddress((void**)&kl,  g_Klo);
    cudaGetSymbolAddress((void**)&vth, g_Vthi); cudaGetSymbolAddress((void**)&vtl, g_Vtlo);
    cudaGetSymbolAddress((void**)&chh, g_Ch);   cudaGetSymbolAddress((void**)&cll, g_Cl);

    const int smemBig = 4 * TILEB;   // 73728
    cudaFuncSetAttribute(mma_gemm128, cudaFuncAttributeMaxDynamicSharedMemorySize, smemBig);
    cudaFuncSetAttribute(flash_attn,  cudaFuncAttributeMaxDynamicSharedMemorySize, FLASH_SMEM);

    // preprocessing
    detect_mask_kernel<<<1, 32>>>((const unsigned int*)mask);
    norm_mask_kernel<<<(int)((SS + 255) / 256), 256>>>(mask);
    conv_x_kernel<<<(int)(((size_t)SDIM * CDIM / 2 + 255) / 256), 256>>>(hidden);
    dim3 tb(32, 8), tg(CDIM / 32, CDIM / 32);
    transpose_w_kernel<<<tg, tb>>>(Wq, wqh, wql);
    transpose_w_kernel<<<tg, tb>>>(Wk, wkh, wkl);
    transpose_w_kernel<<<tg, tb>>>(Wv, wvh, wvl);
    transpose_w_kernel<<<tg, tb>>>(Wo, woh, wol);

    // projections
    dim3 gProj(CDIM / 128, SDIM / 128);
    mma_gemm128<<<gProj, 256, smemBig>>>(xh, xl, CDIM, wqh, wql, CDIM, CDIM / 64, 0, qh, ql, nullptr, nullptr);
    mma_gemm128<<<gProj, 256, smemBig>>>(xh, xl, CDIM, wkh, wkl, CDIM, CDIM / 64, 0, kh, kl, nullptr, nullptr);
    mma_gemm128<<<gProj, 256, smemBig>>>(xh, xl, CDIM, wvh, wvl, CDIM, CDIM / 64, 1, vth, vtl, nullptr, nullptr);

    // fused attention
    dim3 gF(SDIM / 128, NHEAD);
    flash_attn<<<gF, 256, FLASH_SMEM>>>();

    // output projection
    dim3 gOut(CDIM / 128, SDIM / 128);
    mma_gemm128<<<gOut, 256, smemBig>>>(chh, cll, CDIM, woh, wol, CDIM, CDIM / 64, 2, nullptr, nullptr, bo, out);
}